// round 2
// baseline (speedup 1.0000x reference)
#include <cuda_runtime.h>
#include <math.h>

#define BB 8
#define NLAT 256
#define DLAT 512
#define HW 16384
#define IND 29

// ---------------- scratch (static device globals; no allocation) ------------
__device__ float g_lat[BB * NLAT * DLAT];
__device__ float g_ln [BB * NLAT * DLAT];
__device__ float g_q  [BB * NLAT * DLAT];
__device__ float g_kv [BB * NLAT * 2 * DLAT];
__device__ float g_ao [BB * NLAT * DLAT];
__device__ float g_ff1[BB * NLAT * 4096];
__device__ float g_ff2[BB * NLAT * 2048];
__device__ float g_ckv[BB * NLAT * 128];
__device__ float g_data[BB * HW * IND];

// ---------------------------------------------------------------------------
// lat = (x @ W_l2l + b_l2l).reshape(B,N,D) + latents
// one thread per output column j, 8 batch accumulators, W read once coalesced
// ---------------------------------------------------------------------------
__global__ __launch_bounds__(256) void l2l_kernel(
    const float* __restrict__ x, const float* __restrict__ W,
    const float* __restrict__ bias, const float* __restrict__ latents)
{
    __shared__ float xs[4096];
    for (int i = threadIdx.x; i < 4096; i += 256) xs[i] = x[i];
    __syncthreads();
    int j = blockIdx.x * 256 + threadIdx.x;   // 0..131071
    float acc[8];
#pragma unroll
    for (int b = 0; b < 8; b++) acc[b] = 0.f;
    const float* wp = W + j;
#pragma unroll 4
    for (int k = 0; k < 512; k++) {
        float w = wp[(size_t)k * 131072];
#pragma unroll
        for (int b = 0; b < 8; b++) acc[b] = fmaf(xs[b * 512 + k], w, acc[b]);
    }
    float add = bias[j] + latents[j];
#pragma unroll
    for (int b = 0; b < 8; b++) g_lat[b * 131072 + j] = acc[b] + add;
}

// ---------------------------------------------------------------------------
// data init: [zeros(3) | sin(6)|cos(6)|pos (axis0) | sin|cos|pos (axis1)]
// ---------------------------------------------------------------------------
__global__ void init_data_kernel()
{
    int idx = blockIdx.x * blockDim.x + threadIdx.x;
    if (idx >= HW * IND) return;
    int p = idx / IND, c = idx - p * IND;
    int h = p >> 7, w = p & 127;
    float val = 0.f;
    if (c >= 3) {
        int e = c - 3;
        int axis = e / 13;
        int k = e - axis * 13;
        float coord = -1.f + (2.f / 127.f) * (float)(axis == 0 ? h : w);
        if (k == 12) {
            val = coord;
        } else {
            int band = (k >= 6) ? k - 6 : k;
            float ee = 1.f + (float)band * (1.3219280948873623f / 5.f); // linspace(1, log2(5), 6)
            float sc = exp2f(ee);
            float xp = coord * sc * 3.14159265358979323846f;
            val = (k >= 6) ? cosf(xp) : sinf(xp);
        }
    }
#pragma unroll
    for (int b = 0; b < 8; b++) g_data[b * (HW * IND) + idx] = val;
}

// ---------------------------------------------------------------------------
// LayerNorm over 512 (128 threads per row, float4)
// ---------------------------------------------------------------------------
__global__ __launch_bounds__(128) void ln512_kernel(
    const float* __restrict__ in, const float* __restrict__ gg,
    const float* __restrict__ bbv, float* __restrict__ out)
{
    __shared__ float red[4];
    const int row = blockIdx.x, t = threadIdx.x;
    float4 v = reinterpret_cast<const float4*>(in + row * 512)[t];
    float s = (v.x + v.y) + (v.z + v.w);
#pragma unroll
    for (int o = 16; o; o >>= 1) s += __shfl_xor_sync(0xffffffffu, s, o);
    if ((t & 31) == 0) red[t >> 5] = s;
    __syncthreads();
    float mean = ((red[0] + red[1]) + (red[2] + red[3])) * (1.f / 512.f);
    __syncthreads();
    float dx = v.x - mean, dy = v.y - mean, dz = v.z - mean, dw = v.w - mean;
    float ss = (dx * dx + dy * dy) + (dz * dz + dw * dw);
#pragma unroll
    for (int o = 16; o; o >>= 1) ss += __shfl_xor_sync(0xffffffffu, ss, o);
    if ((t & 31) == 0) red[t >> 5] = ss;
    __syncthreads();
    float var = ((red[0] + red[1]) + (red[2] + red[3])) * (1.f / 512.f);
    float rstd = rsqrtf(var + 1e-5f);
    float4 gv = reinterpret_cast<const float4*>(gg)[t];
    float4 bv = reinterpret_cast<const float4*>(bbv)[t];
    float4 ov;
    ov.x = dx * rstd * gv.x + bv.x;
    ov.y = dy * rstd * gv.y + bv.y;
    ov.z = dz * rstd * gv.z + bv.z;
    ov.w = dw * rstd * gv.w + bv.w;
    reinterpret_cast<float4*>(out + row * 512)[t] = ov;
}

// ---------------------------------------------------------------------------
// Tiled fp32 GEMM: C(MxN) = A(MxK) @ B(KxN) [+ bias(N)] [+ res(MxN)]
// BM=BN=64, BK=16, TM=TN=4, 256 threads. All dims are exact multiples.
// ---------------------------------------------------------------------------
template <int BM, int BN, int BK, int TM, int TN>
__global__ __launch_bounds__(256) void gemm_k(
    const float* __restrict__ A, const float* __restrict__ Bm,
    const float* __restrict__ bias, const float* __restrict__ res,
    float* __restrict__ C, int M, int N, int K)
{
    __shared__ float As[BK][BM];
    __shared__ float Bs[BK][BN];
    const int bm = blockIdx.y * BM, bn = blockIdx.x * BN;
    const int tid = threadIdx.x;
    constexpr int NTX = BN / TN;
    const int tx = tid % NTX, ty = tid / NTX;
    float acc[TM][TN];
#pragma unroll
    for (int i = 0; i < TM; i++)
#pragma unroll
        for (int j = 0; j < TN; j++) acc[i][j] = 0.f;

    for (int k0 = 0; k0 < K; k0 += BK) {
#pragma unroll
        for (int i = 0; i < (BM * BK) / 256; i++) {
            int idx = i * 256 + tid;
            int m = idx / BK, k = idx - m * BK;
            As[k][m] = A[(size_t)(bm + m) * K + k0 + k];
        }
#pragma unroll
        for (int i = 0; i < (BK * BN) / 256; i++) {
            int idx = i * 256 + tid;
            int k = idx / BN, n = idx - k * BN;
            Bs[k][n] = Bm[(size_t)(k0 + k) * N + bn + n];
        }
        __syncthreads();
#pragma unroll
        for (int k = 0; k < BK; k++) {
            float a[TM], bv[TN];
#pragma unroll
            for (int i = 0; i < TM; i++) a[i] = As[k][ty * TM + i];
#pragma unroll
            for (int j = 0; j < TN; j++) bv[j] = Bs[k][tx * TN + j];
#pragma unroll
            for (int i = 0; i < TM; i++)
#pragma unroll
                for (int j = 0; j < TN; j++)
                    acc[i][j] = fmaf(a[i], bv[j], acc[i][j]);
        }
        __syncthreads();
    }
#pragma unroll
    for (int i = 0; i < TM; i++) {
        int row = bm + ty * TM + i;
#pragma unroll
        for (int j = 0; j < TN; j++) {
            int col = bn + tx * TN + j;
            float v = acc[i][j];
            if (bias) v += bias[col];
            if (res)  v += res[(size_t)row * N + col];
            C[(size_t)row * N + col] = v;
        }
    }
}

// ---------------------------------------------------------------------------
// GEGLU elementwise (latent FF): ff2 = a * gelu_exact(g)
// ---------------------------------------------------------------------------
__global__ void geglu_kernel()
{
    int idx = blockIdx.x * blockDim.x + threadIdx.x;
    if (idx >= 2048 * 2048) return;
    int r = idx >> 11, j = idx & 2047;
    float a  = g_ff1[r * 4096 + j];
    float g2 = g_ff1[r * 4096 + 2048 + j];
    g_ff2[idx] = a * 0.5f * g2 * (1.f + erff(g2 * 0.70710678118654752f));
}

// ---------------------------------------------------------------------------
// Latent self-attn (8 heads, dh=64, n=m=256). CTA = (head, batch),
// one thread per query row, K/V in smem, no-max streaming softmax.
// ---------------------------------------------------------------------------
__global__ __launch_bounds__(256) void lat_attn_k()
{
    extern __shared__ float sm[];
    float* Ks = sm;                 // 256*64
    float* Vs = sm + NLAT * 64;     // 256*64
    const int h = blockIdx.x, b = blockIdx.y;
    const int tid = threadIdx.x;

    for (int i = tid; i < NLAT * 64; i += 256) {
        int j = i >> 6, d = i & 63;
        Ks[i] = g_kv[(size_t)(b * NLAT + j) * 1024 + h * 64 + d];
        Vs[i] = g_kv[(size_t)(b * NLAT + j) * 1024 + 512 + h * 64 + d];
    }
    __syncthreads();

    float q[64];
    {
        const float4* qg = reinterpret_cast<const float4*>(&g_q[(size_t)(b * NLAT + tid) * 512 + h * 64]);
#pragma unroll
        for (int dd = 0; dd < 16; dd++) {
            float4 t = qg[dd];
            q[4 * dd + 0] = t.x; q[4 * dd + 1] = t.y; q[4 * dd + 2] = t.z; q[4 * dd + 3] = t.w;
        }
    }
    float out[64];
#pragma unroll
    for (int d = 0; d < 64; d++) out[d] = 0.f;
    float ssum = 0.f;
    const float4* K4 = reinterpret_cast<const float4*>(Ks);
    const float4* V4 = reinterpret_cast<const float4*>(Vs);
    for (int j = 0; j < NLAT; j++) {
        float s = 0.f;
#pragma unroll
        for (int dd = 0; dd < 16; dd++) {
            float4 k4 = K4[j * 16 + dd];
            s = fmaf(q[4 * dd + 0], k4.x, s);
            s = fmaf(q[4 * dd + 1], k4.y, s);
            s = fmaf(q[4 * dd + 2], k4.z, s);
            s = fmaf(q[4 * dd + 3], k4.w, s);
        }
        float p = __expf(s * 0.125f);
        ssum += p;
#pragma unroll
        for (int dd = 0; dd < 16; dd++) {
            float4 v4 = V4[j * 16 + dd];
            out[4 * dd + 0] = fmaf(p, v4.x, out[4 * dd + 0]);
            out[4 * dd + 1] = fmaf(p, v4.y, out[4 * dd + 1]);
            out[4 * dd + 2] = fmaf(p, v4.z, out[4 * dd + 2]);
            out[4 * dd + 3] = fmaf(p, v4.w, out[4 * dd + 3]);
        }
    }
    float inv = 1.f / ssum;
    float4* og = reinterpret_cast<float4*>(&g_ao[(size_t)(b * NLAT + tid) * 512 + h * 64]);
#pragma unroll
    for (int dd = 0; dd < 16; dd++) {
        float4 t;
        t.x = out[4 * dd + 0] * inv; t.y = out[4 * dd + 1] * inv;
        t.z = out[4 * dd + 2] * inv; t.w = out[4 * dd + 3] * inv;
        og[dd] = t;
    }
}

// ---------------------------------------------------------------------------
// Fused cross-attention over data rows (1 head, dh=64, ctx 256):
// data += softmax(LN(data)@Wq @ K^T / 8) V @ Wo + bo
// CTA = 256 rows of one batch; K,V,weights,rows staged in smem.
// ---------------------------------------------------------------------------
__global__ __launch_bounds__(256) void cross_attn_k(
    const float* __restrict__ Wq, const float* __restrict__ Wo,
    const float* __restrict__ bo, const float* __restrict__ lng,
    const float* __restrict__ lnb)
{
    extern __shared__ float sm[];
    float* Ks    = sm;              // 16384
    float* Vs    = Ks + 16384;      // 16384
    float* Wqs   = Vs + 16384;      // 1856
    float* Wos   = Wqs + 1856;      // 1856
    float* cbo   = Wos + 1856;      // 29
    float* cg    = cbo + 29;        // 29
    float* cb    = cg + 29;         // 29 (pad to 96)
    float* stage = Wos + 1856 + 96; // 7424
    float* xns   = stage + 7424;    // 7424

    const int b = blockIdx.y;
    const int tid = threadIdx.x;
    const int base = (b * HW + blockIdx.x * 256) * IND;

    for (int i = tid; i < 16384; i += 256) {
        int j = i >> 6, d = i & 63;
        Ks[i] = g_ckv[(b * NLAT + j) * 128 + d];
        Vs[i] = g_ckv[(b * NLAT + j) * 128 + 64 + d];
    }
    for (int i = tid; i < 1856; i += 256) { Wqs[i] = Wq[i]; Wos[i] = Wo[i]; }
    if (tid < 29) { cbo[tid] = bo[tid]; cg[tid] = lng[tid]; cb[tid] = lnb[tid]; }
    for (int i = tid; i < 256 * IND; i += 256) stage[i] = g_data[base + i];
    __syncthreads();

    // LayerNorm of own row (stride 29 is odd -> conflict-free)
    float mean = 0.f;
    for (int j = 0; j < IND; j++) mean += stage[tid * IND + j];
    mean *= (1.f / 29.f);
    float var = 0.f;
    for (int j = 0; j < IND; j++) { float d0 = stage[tid * IND + j] - mean; var = fmaf(d0, d0, var); }
    float rstd = rsqrtf(var * (1.f / 29.f) + 1e-5f);
    for (int j = 0; j < IND; j++)
        xns[tid * IND + j] = (stage[tid * IND + j] - mean) * rstd * cg[j] + cb[j];

    // q = xn @ Wq   (29 x 64)
    float q[64];
#pragma unroll
    for (int d = 0; d < 64; d++) q[d] = 0.f;
    for (int j = 0; j < IND; j++) {
        float xj = xns[tid * IND + j];
        const float4* w4 = reinterpret_cast<const float4*>(Wqs + j * 64);
#pragma unroll
        for (int dd = 0; dd < 16; dd++) {
            float4 w = w4[dd];
            q[4 * dd + 0] = fmaf(xj, w.x, q[4 * dd + 0]);
            q[4 * dd + 1] = fmaf(xj, w.y, q[4 * dd + 1]);
            q[4 * dd + 2] = fmaf(xj, w.z, q[4 * dd + 2]);
            q[4 * dd + 3] = fmaf(xj, w.w, q[4 * dd + 3]);
        }
    }

    // streaming softmax + AV (scores tiny; shift-free softmax is exact up to fp)
    float out[64];
#pragma unroll
    for (int d = 0; d < 64; d++) out[d] = 0.f;
    float ssum = 0.f;
    const float4* K4 = reinterpret_cast<const float4*>(Ks);
    const float4* V4 = reinterpret_cast<const float4*>(Vs);
    for (int j = 0; j < NLAT; j++) {
        float s = 0.f;
#pragma unroll
        for (int dd = 0; dd < 16; dd++) {
            float4 k4 = K4[j * 16 + dd];
            s = fmaf(q[4 * dd + 0], k4.x, s);
            s = fmaf(q[4 * dd + 1], k4.y, s);
            s = fmaf(q[4 * dd + 2], k4.z, s);
            s = fmaf(q[4 * dd + 3], k4.w, s);
        }
        float p = __expf(s * 0.125f);
        ssum += p;
#pragma unroll
        for (int dd = 0; dd < 16; dd++) {
            float4 v4 = V4[j * 16 + dd];
            out[4 * dd + 0] = fmaf(p, v4.x, out[4 * dd + 0]);
            out[4 * dd + 1] = fmaf(p, v4.y, out[4 * dd + 1]);
            out[4 * dd + 2] = fmaf(p, v4.z, out[4 * dd + 2]);
            out[4 * dd + 3] = fmaf(p, v4.w, out[4 * dd + 3]);
        }
    }
    float inv = 1.f / ssum;
#pragma unroll
    for (int d = 0; d < 64; d++) out[d] *= inv;

    // out-proj + bias + residual, write back
    for (int c = 0; c < IND; c++) {
        float r = cbo[c];
#pragma unroll
        for (int d = 0; d < 64; d++) r = fmaf(out[d], Wos[d * IND + c], r);
        g_data[base + tid * IND + c] = stage[tid * IND + c] + r;
    }
}

// ---------------------------------------------------------------------------
// Fused data GEGLU FF: data += (a * gelu(g)) @ W2 + b2 where [a|g] = LN(data)@W1+b1
// one thread per row; weights + rows staged in smem.
// ---------------------------------------------------------------------------
__global__ __launch_bounds__(256) void data_ff_k(
    const float* __restrict__ W1, const float* __restrict__ b1,
    const float* __restrict__ W2, const float* __restrict__ b2,
    const float* __restrict__ lng, const float* __restrict__ lnb)
{
    extern __shared__ float sm[];
    float* W1s   = sm;              // 6728
    float* b1s   = W1s + 6728;      // 232
    float* W2s   = b1s + 232;       // 3364
    float* cb2   = W2s + 3364;      // 29
    float* cg    = cb2 + 29;        // 29
    float* cb    = cg + 29;         // 29 (pad to 96)
    float* stage = cb2 + 96;        // 7424
    float* xns   = stage + 7424;    // 7424

    const int tid = threadIdx.x;
    const int base = blockIdx.x * 256 * IND;

    for (int i = tid; i < 6728; i += 256) W1s[i] = W1[i];
    for (int i = tid; i < 3364; i += 256) W2s[i] = W2[i];
    if (tid < 232) b1s[tid] = b1[tid];
    if (tid < 29) { cb2[tid] = b2[tid]; cg[tid] = lng[tid]; cb[tid] = lnb[tid]; }
    for (int i = tid; i < 256 * IND; i += 256) stage[i] = g_data[base + i];
    __syncthreads();

    float mean = 0.f;
    for (int j = 0; j < IND; j++) mean += stage[tid * IND + j];
    mean *= (1.f / 29.f);
    float var = 0.f;
    for (int j = 0; j < IND; j++) { float d0 = stage[tid * IND + j] - mean; var = fmaf(d0, d0, var); }
    float rstd = rsqrtf(var * (1.f / 29.f) + 1e-5f);
    for (int j = 0; j < IND; j++)
        xns[tid * IND + j] = (stage[tid * IND + j] - mean) * rstd * cg[j] + cb[j];

    float res[29];
#pragma unroll
    for (int c = 0; c < IND; c++) res[c] = 0.f;

    for (int u = 0; u < 116; u++) {
        float a = b1s[u], g = b1s[116 + u];
        for (int j = 0; j < IND; j++) {
            float xj = xns[tid * IND + j];
            a = fmaf(xj, W1s[j * 232 + u], a);
            g = fmaf(xj, W1s[j * 232 + u + 116], g);
        }
        float hv = a * 0.5f * g * (1.f + erff(g * 0.70710678118654752f));
#pragma unroll
        for (int c = 0; c < IND; c++) res[c] = fmaf(hv, W2s[u * IND + c], res[c]);
    }
#pragma unroll
    for (int c = 0; c < IND; c++)
        g_data[base + tid * IND + c] = stage[tid * IND + c] + res[c] + cb2[c];
}

// ---------------------------------------------------------------------------
// Output: out[b,h,w,c] = data[b, h*128+w, c] for c < 3
// ---------------------------------------------------------------------------
__global__ void out_kernel(float* __restrict__ out)
{
    int idx = blockIdx.x * blockDim.x + threadIdx.x;
    if (idx >= BB * HW * 3) return;
    int b = idx / (HW * 3);
    int rem = idx - b * HW * 3;
    int p = rem / 3, c = rem - p * 3;
    out[idx] = g_data[(b * HW + p) * IND + c];
}

// ---------------------------------------------------------------------------
extern "C" void kernel_launch(void* const* d_in, const int* in_sizes, int n_in,
                              void* d_out, int out_size)
{
    const float* x        = (const float*)d_in[0];
    const float* latents  = (const float*)d_in[1];
    const float* W_l2l    = (const float*)d_in[2];
    const float* b_l2l    = (const float*)d_in[3];
    const float* ca_ln_q_g = (const float*)d_in[4];
    const float* ca_ln_q_b = (const float*)d_in[5];
    const float* ca_ln_c_g = (const float*)d_in[6];
    const float* ca_ln_c_b = (const float*)d_in[7];
    const float* ca_Wq    = (const float*)d_in[8];
    const float* ca_Wkv   = (const float*)d_in[9];
    const float* ca_Wo    = (const float*)d_in[10];
    const float* ca_bo    = (const float*)d_in[11];
    const float* cf_ln_g  = (const float*)d_in[12];
    const float* cf_ln_b  = (const float*)d_in[13];
    const float* cf_W1    = (const float*)d_in[14];
    const float* cf_b1    = (const float*)d_in[15];
    const float* cf_W2    = (const float*)d_in[16];
    const float* cf_b2    = (const float*)d_in[17];
    const float* la_ln_g  = (const float*)d_in[18];
    const float* la_ln_b  = (const float*)d_in[19];
    const float* la_Wq    = (const float*)d_in[20];
    const float* la_Wkv   = (const float*)d_in[21];
    const float* la_Wo    = (const float*)d_in[22];
    const float* la_bo    = (const float*)d_in[23];
    const float* lf_ln_g  = (const float*)d_in[24];
    const float* lf_ln_b  = (const float*)d_in[25];
    const float* lf_W1    = (const float*)d_in[26];
    const float* lf_b1    = (const float*)d_in[27];
    const float* lf_W2    = (const float*)d_in[28];
    const float* lf_b2    = (const float*)d_in[29];

    float *p_lat, *p_ln, *p_q, *p_kv, *p_ao, *p_ff1, *p_ff2, *p_ckv;
    cudaGetSymbolAddress((void**)&p_lat, g_lat);
    cudaGetSymbolAddress((void**)&p_ln,  g_ln);
    cudaGetSymbolAddress((void**)&p_q,   g_q);
    cudaGetSymbolAddress((void**)&p_kv,  g_kv);
    cudaGetSymbolAddress((void**)&p_ao,  g_ao);
    cudaGetSymbolAddress((void**)&p_ff1, g_ff1);
    cudaGetSymbolAddress((void**)&p_ff2, g_ff2);
    cudaGetSymbolAddress((void**)&p_ckv, g_ckv);

    const int LAT_SMEM   = 2 * NLAT * 64 * 4;                              // 131072 B
    const int CROSS_SMEM = (16384 + 16384 + 1856 + 1856 + 96 + 7424 + 7424) * 4; // 205696 B
    const int FF_SMEM    = (6728 + 232 + 3364 + 96 + 7424 + 7424) * 4;    // 101072 B
    cudaFuncSetAttribute(lat_attn_k,   cudaFuncAttributeMaxDynamicSharedMemorySize, LAT_SMEM);
    cudaFuncSetAttribute(cross_attn_k, cudaFuncAttributeMaxDynamicSharedMemorySize, CROSS_SMEM);
    cudaFuncSetAttribute(data_ff_k,    cudaFuncAttributeMaxDynamicSharedMemorySize, FF_SMEM);

    l2l_kernel<<<512, 256>>>(x, W_l2l, b_l2l, latents);
    init_data_kernel<<<(HW * IND + 255) / 256, 256>>>();

    for (int i = 0; i < 4; i++) {
        // ---- latent self-attention block ----
        ln512_kernel<<<2048, 128>>>(p_lat, la_ln_g + i * 512, la_ln_b + i * 512, p_ln);
        gemm_k<64, 64, 16, 4, 4><<<dim3(8, 32), 256>>>(p_ln, la_Wq + (size_t)i * 262144,
                                                       nullptr, nullptr, p_q, 2048, 512, 512);
        gemm_k<64, 64, 16, 4, 4><<<dim3(16, 32), 256>>>(p_ln, la_Wkv + (size_t)i * 524288,
                                                        nullptr, nullptr, p_kv, 2048, 1024, 512);
        lat_attn_k<<<dim3(8, 8), 256, LAT_SMEM>>>();
        gemm_k<64, 64, 16, 4, 4><<<dim3(8, 32), 256>>>(p_ao, la_Wo + (size_t)i * 262144,
                                                       la_bo + i * 512, p_lat, p_lat, 2048, 512, 512);
        // ---- latent GEGLU FF ----
        ln512_kernel<<<2048, 128>>>(p_lat, lf_ln_g + i * 512, lf_ln_b + i * 512, p_ln);
        gemm_k<64, 64, 16, 4, 4><<<dim3(64, 32), 256>>>(p_ln, lf_W1 + (size_t)i * 2097152,
                                                        lf_b1 + i * 4096, nullptr, p_ff1, 2048, 4096, 512);
        geglu_kernel<<<16384, 256>>>();
        gemm_k<64, 64, 16, 4, 4><<<dim3(8, 32), 256>>>(p_ff2, lf_W2 + (size_t)i * 1048576,
                                                       lf_b2 + i * 512, p_lat, p_lat, 2048, 512, 2048);
        // ---- cross attention (data <- latents) ----
        ln512_kernel<<<2048, 128>>>(p_lat, ca_ln_c_g + i * 512, ca_ln_c_b + i * 512, p_ln);
        gemm_k<64, 64, 16, 4, 4><<<dim3(2, 32), 256>>>(p_ln, ca_Wkv + (size_t)i * 65536,
                                                       nullptr, nullptr, p_ckv, 2048, 128, 512);
        cross_attn_k<<<dim3(64, 8), 256, CROSS_SMEM>>>(ca_Wq + i * 1856, ca_Wo + i * 1856,
                                                       ca_bo + i * 29, ca_ln_q_g + i * 29, ca_ln_q_b + i * 29);
        // ---- data GEGLU FF ----
        data_ff_k<<<512, 256, FF_SMEM>>>(cf_W1 + i * 6728, cf_b1 + i * 232,
                                         cf_W2 + i * 3364, cf_b2 + i * 29,
                                         cf_ln_g + i * 29, cf_ln_b + i * 29);
    }

    out_kernel<<<(BB * HW * 3 + 255) / 256, 256>>>((float*)d_out);
}

// round 3
// speedup vs baseline: 1.0870x; 1.0870x over previous
#include <cuda_runtime.h>
#include <math.h>

#define BB 8
#define NLAT 256
#define DLAT 512
#define HW 16384
#define IND 29

typedef unsigned long long ull;

// ---------------- f32x2 helpers (FFMA2 path, PTX-only) ----------------------
__device__ __forceinline__ ull pack2(float lo, float hi) {
    ull r; asm("mov.b64 %0, {%1, %2};" : "=l"(r) : "f"(lo), "f"(hi)); return r;
}
__device__ __forceinline__ ull pack2s(float v) { return pack2(v, v); }
__device__ __forceinline__ void unpack2(ull p, float& lo, float& hi) {
    asm("mov.b64 {%0, %1}, %2;" : "=f"(lo), "=f"(hi) : "l"(p));
}
__device__ __forceinline__ ull fma2(ull a, ull b, ull c) {
    ull d; asm("fma.rn.f32x2 %0, %1, %2, %3;" : "=l"(d) : "l"(a), "l"(b), "l"(c)); return d;
}
__device__ __forceinline__ ull add2(ull a, ull b) {
    ull d; asm("add.rn.f32x2 %0, %1, %2;" : "=l"(d) : "l"(a), "l"(b)); return d;
}
__device__ __forceinline__ ull mul2(ull a, ull b) {
    ull d; asm("mul.rn.f32x2 %0, %1, %2;" : "=l"(d) : "l"(a), "l"(b)); return d;
}

// ---------------- scratch (static device globals; no allocation) ------------
__device__ float g_lat[BB * NLAT * DLAT];
__device__ float g_ln [BB * NLAT * DLAT];
__device__ float g_q  [BB * NLAT * DLAT];
__device__ float g_kv [BB * NLAT * 2 * DLAT];
__device__ float g_ao [BB * NLAT * DLAT];
__device__ float g_ff1[BB * NLAT * 4096];
__device__ float g_ff2[BB * NLAT * 2048];
__device__ float g_ckv[BB * NLAT * 128];
__device__ float g_data[BB * HW * IND];

// ---------------------------------------------------------------------------
// lat = (x @ W_l2l + b_l2l).reshape(B,N,D) + latents   (HBM-bound, keep)
// ---------------------------------------------------------------------------
__global__ __launch_bounds__(256) void l2l_kernel(
    const float* __restrict__ x, const float* __restrict__ W,
    const float* __restrict__ bias, const float* __restrict__ latents)
{
    __shared__ float xs[4096];
    for (int i = threadIdx.x; i < 4096; i += 256) xs[i] = x[i];
    __syncthreads();
    int j = blockIdx.x * 256 + threadIdx.x;
    float acc[8];
#pragma unroll
    for (int b = 0; b < 8; b++) acc[b] = 0.f;
    const float* wp = W + j;
#pragma unroll 4
    for (int k = 0; k < 512; k++) {
        float w = wp[(size_t)k * 131072];
#pragma unroll
        for (int b = 0; b < 8; b++) acc[b] = fmaf(xs[b * 512 + k], w, acc[b]);
    }
    float add = bias[j] + latents[j];
#pragma unroll
    for (int b = 0; b < 8; b++) g_lat[b * 131072 + j] = acc[b] + add;
}

// ---------------------------------------------------------------------------
// data init
// ---------------------------------------------------------------------------
__global__ void init_data_kernel()
{
    int idx = blockIdx.x * blockDim.x + threadIdx.x;
    if (idx >= HW * IND) return;
    int p = idx / IND, c = idx - p * IND;
    int h = p >> 7, w = p & 127;
    float val = 0.f;
    if (c >= 3) {
        int e = c - 3;
        int axis = e / 13;
        int k = e - axis * 13;
        float coord = -1.f + (2.f / 127.f) * (float)(axis == 0 ? h : w);
        if (k == 12) {
            val = coord;
        } else {
            int band = (k >= 6) ? k - 6 : k;
            float ee = 1.f + (float)band * (1.3219280948873623f / 5.f);
            float sc = exp2f(ee);
            float xp = coord * sc * 3.14159265358979323846f;
            val = (k >= 6) ? cosf(xp) : sinf(xp);
        }
    }
#pragma unroll
    for (int b = 0; b < 8; b++) g_data[b * (HW * IND) + idx] = val;
}

// ---------------------------------------------------------------------------
// LayerNorm over 512
// ---------------------------------------------------------------------------
__global__ __launch_bounds__(128) void ln512_kernel(
    const float* __restrict__ in, const float* __restrict__ gg,
    const float* __restrict__ bbv, float* __restrict__ out)
{
    __shared__ float red[4];
    const int row = blockIdx.x, t = threadIdx.x;
    float4 v = reinterpret_cast<const float4*>(in + row * 512)[t];
    float s = (v.x + v.y) + (v.z + v.w);
#pragma unroll
    for (int o = 16; o; o >>= 1) s += __shfl_xor_sync(0xffffffffu, s, o);
    if ((t & 31) == 0) red[t >> 5] = s;
    __syncthreads();
    float mean = ((red[0] + red[1]) + (red[2] + red[3])) * (1.f / 512.f);
    __syncthreads();
    float dx = v.x - mean, dy = v.y - mean, dz = v.z - mean, dw = v.w - mean;
    float ss = (dx * dx + dy * dy) + (dz * dz + dw * dw);
#pragma unroll
    for (int o = 16; o; o >>= 1) ss += __shfl_xor_sync(0xffffffffu, ss, o);
    if ((t & 31) == 0) red[t >> 5] = ss;
    __syncthreads();
    float var = ((red[0] + red[1]) + (red[2] + red[3])) * (1.f / 512.f);
    float rstd = rsqrtf(var + 1e-5f);
    float4 gv = reinterpret_cast<const float4*>(gg)[t];
    float4 bv = reinterpret_cast<const float4*>(bbv)[t];
    float4 ov;
    ov.x = dx * rstd * gv.x + bv.x;
    ov.y = dy * rstd * gv.y + bv.y;
    ov.z = dz * rstd * gv.z + bv.z;
    ov.w = dw * rstd * gv.w + bv.w;
    reinterpret_cast<float4*>(out + row * 512)[t] = ov;
}

// ---------------------------------------------------------------------------
// FFMA2 tiled GEMM: C = A @ B [+bias(N)] [+res]; pairs along N.
// 256 threads; NTX = BN/TN must be 16 and BM/TM must be 16.
// ---------------------------------------------------------------------------
template <int BM, int BN, int BK, int TM, int TN>
__global__ __launch_bounds__(256, 2) void gemm2_k(
    const float* __restrict__ A, const float* __restrict__ Bm,
    const float* __restrict__ bias, const float* __restrict__ res,
    float* __restrict__ C, int M, int N, int K)
{
    constexpr int LDA = BM + 4;
    constexpr int NTX = BN / TN;
    constexpr int ATH = BM * BK / 4;
    constexpr int KQ  = BK / 4;
    __shared__ float As[BK][LDA];
    __shared__ float Bs[BK][BN];
    const int bm = blockIdx.y * BM, bn = blockIdx.x * BN;
    const int tid = threadIdx.x;
    const int tx = tid % NTX, ty = tid / NTX;

    const int am = tid / KQ, ak = (tid % KQ) * 4;
    const int bk = tid / (BN / 4), bn4 = (tid % (BN / 4)) * 4;

    ull acc[TM][TN / 2];
#pragma unroll
    for (int i = 0; i < TM; i++)
#pragma unroll
        for (int j = 0; j < TN / 2; j++) acc[i][j] = 0ull;

    float4 pa, pb;
    if (tid < ATH) pa = *reinterpret_cast<const float4*>(&A[(size_t)(bm + am) * K + ak]);
    pb = *reinterpret_cast<const float4*>(&Bm[(size_t)bk * N + bn + bn4]);

    for (int k0 = 0; k0 < K; k0 += BK) {
        if (tid < ATH) {
            As[ak + 0][am] = pa.x; As[ak + 1][am] = pa.y;
            As[ak + 2][am] = pa.z; As[ak + 3][am] = pa.w;
        }
        *reinterpret_cast<float4*>(&Bs[bk][bn4]) = pb;
        __syncthreads();
        int kn = k0 + BK;
        if (kn < K) {
            if (tid < ATH) pa = *reinterpret_cast<const float4*>(&A[(size_t)(bm + am) * K + kn + ak]);
            pb = *reinterpret_cast<const float4*>(&Bm[(size_t)(kn + bk) * N + bn + bn4]);
        }
#pragma unroll
        for (int k = 0; k < BK; k++) {
            ull b2[TN / 2];
            const ulonglong2* bp = reinterpret_cast<const ulonglong2*>(&Bs[k][tx * TN]);
#pragma unroll
            for (int j = 0; j < TN / 4; j++) {
                ulonglong2 t2 = bp[j];
                b2[2 * j] = t2.x; b2[2 * j + 1] = t2.y;
            }
            ull ap[TM];
#pragma unroll
            for (int i = 0; i < TM; i += 4) {
                float4 av = *reinterpret_cast<const float4*>(&As[k][ty * TM + i]);
                ap[i + 0] = pack2s(av.x); ap[i + 1] = pack2s(av.y);
                ap[i + 2] = pack2s(av.z); ap[i + 3] = pack2s(av.w);
            }
#pragma unroll
            for (int i = 0; i < TM; i++)
#pragma unroll
                for (int j = 0; j < TN / 2; j++)
                    acc[i][j] = fma2(ap[i], b2[j], acc[i][j]);
        }
        __syncthreads();
    }

    float bv[TN];
#pragma unroll
    for (int j = 0; j < TN; j++) bv[j] = 0.f;
    if (bias) {
#pragma unroll
        for (int j = 0; j < TN; j += 4) {
            float4 t = *reinterpret_cast<const float4*>(&bias[bn + tx * TN + j]);
            bv[j] = t.x; bv[j + 1] = t.y; bv[j + 2] = t.z; bv[j + 3] = t.w;
        }
    }
#pragma unroll
    for (int i = 0; i < TM; i++) {
        size_t row = (size_t)(bm + ty * TM + i);
        float o[TN];
#pragma unroll
        for (int j = 0; j < TN / 2; j++) unpack2(acc[i][j], o[2 * j], o[2 * j + 1]);
#pragma unroll
        for (int j = 0; j < TN; j++) o[j] += bv[j];
        if (res) {
#pragma unroll
            for (int j = 0; j < TN; j += 4) {
                float4 t = *reinterpret_cast<const float4*>(&res[row * N + bn + tx * TN + j]);
                o[j] += t.x; o[j + 1] += t.y; o[j + 2] += t.z; o[j + 3] += t.w;
            }
        }
#pragma unroll
        for (int j = 0; j < TN; j += 4) {
            float4 t; t.x = o[j]; t.y = o[j + 1]; t.z = o[j + 2]; t.w = o[j + 3];
            *reinterpret_cast<float4*>(&C[row * N + bn + tx * TN + j]) = t;
        }
    }
}

// ---------------------------------------------------------------------------
// GEGLU elementwise (latent FF)
// ---------------------------------------------------------------------------
__global__ void geglu_kernel()
{
    int idx = blockIdx.x * blockDim.x + threadIdx.x;
    if (idx >= 2048 * 2048) return;
    int r = idx >> 11, j = idx & 2047;
    float a  = g_ff1[r * 4096 + j];
    float g2 = g_ff1[r * 4096 + 2048 + j];
    g_ff2[idx] = a * 0.5f * g2 * (1.f + erff(g2 * 0.70710678118654752f));
}

// ---------------------------------------------------------------------------
// Latent self-attn (8 heads, dh=64): FFMA2 streaming softmax per query row
// ---------------------------------------------------------------------------
__global__ __launch_bounds__(256) void lat_attn_k()
{
    extern __shared__ float sm[];
    float* Ks = sm;
    float* Vs = sm + NLAT * 64;
    const int h = blockIdx.x, b = blockIdx.y;
    const int tid = threadIdx.x;

    for (int i = tid; i < NLAT * 64; i += 256) {
        int j = i >> 6, d = i & 63;
        Ks[i] = g_kv[(size_t)(b * NLAT + j) * 1024 + h * 64 + d];
        Vs[i] = g_kv[(size_t)(b * NLAT + j) * 1024 + 512 + h * 64 + d];
    }
    __syncthreads();

    ull q2[32];
    {
        const ulonglong2* qg = reinterpret_cast<const ulonglong2*>(
            &g_q[(size_t)(b * NLAT + tid) * 512 + h * 64]);
#pragma unroll
        for (int t = 0; t < 16; t++) { ulonglong2 v = qg[t]; q2[2 * t] = v.x; q2[2 * t + 1] = v.y; }
    }
    ull out2[32];
#pragma unroll
    for (int t = 0; t < 32; t++) out2[t] = 0ull;
    float ssum = 0.f;

    for (int j = 0; j < NLAT; j++) {
        const ulonglong2* kp = reinterpret_cast<const ulonglong2*>(&Ks[j * 64]);
        ull s2a = 0ull, s2b = 0ull;
#pragma unroll
        for (int t = 0; t < 16; t += 2) {
            ulonglong2 k0 = kp[t], k1 = kp[t + 1];
            s2a = fma2(q2[2 * t + 0], k0.x, s2a);
            s2b = fma2(q2[2 * t + 1], k0.y, s2b);
            s2a = fma2(q2[2 * t + 2], k1.x, s2a);
            s2b = fma2(q2[2 * t + 3], k1.y, s2b);
        }
        float l0, h0, l1, h1;
        unpack2(s2a, l0, h0); unpack2(s2b, l1, h1);
        float p = __expf(((l0 + h0) + (l1 + h1)) * 0.125f);
        ssum += p;
        ull p2 = pack2s(p);
        const ulonglong2* vp = reinterpret_cast<const ulonglong2*>(&Vs[j * 64]);
#pragma unroll
        for (int t = 0; t < 16; t++) {
            ulonglong2 vv = vp[t];
            out2[2 * t]     = fma2(p2, vv.x, out2[2 * t]);
            out2[2 * t + 1] = fma2(p2, vv.y, out2[2 * t + 1]);
        }
    }
    ull inv2 = pack2s(1.f / ssum);
    float* og = &g_ao[(size_t)(b * NLAT + tid) * 512 + h * 64];
#pragma unroll
    for (int t = 0; t < 16; t++) {
        ull r0 = mul2(out2[2 * t], inv2), r1 = mul2(out2[2 * t + 1], inv2);
        float4 w;
        unpack2(r0, w.x, w.y); unpack2(r1, w.z, w.w);
        reinterpret_cast<float4*>(og)[t] = w;
    }
}

// ---------------------------------------------------------------------------
// Fused cross-attention (FFMA2): data += softmax(LN(data)Wq K^T/8) V Wo + bo
// ---------------------------------------------------------------------------
__global__ __launch_bounds__(256) void cross_attn_k(
    const float* __restrict__ Wq, const float* __restrict__ Wo,
    const float* __restrict__ bo, const float* __restrict__ lng,
    const float* __restrict__ lnb)
{
    extern __shared__ float sm[];
    float* Ks    = sm;              // 16384
    float* Vs    = Ks + 16384;      // 16384
    float* Wqs   = Vs + 16384;      // 1856
    float* Wot   = Wqs + 1856;      // 1856 transposed [c*64+d]
    float* cbo   = Wot + 1856;      // 29
    float* cg    = cbo + 29;        // 29
    float* cb    = cg + 29;         // 29 (block pads to 96)
    float* stage = cbo + 96;        // 7424
    // total = 16384*2 + 1856*2 + 96 + 7424 = 44000 floats

    const int b = blockIdx.y;
    const int tid = threadIdx.x;
    const int base = (b * HW + blockIdx.x * 256) * IND;

    for (int i = tid; i < 16384; i += 256) {
        int j = i >> 6, d = i & 63;
        Ks[i] = g_ckv[(b * NLAT + j) * 128 + d];
        Vs[i] = g_ckv[(b * NLAT + j) * 128 + 64 + d];
    }
    for (int i = tid; i < 1856; i += 256) {
        Wqs[i] = Wq[i];
        Wot[i] = Wo[(i & 63) * IND + (i >> 6)];
    }
    if (tid < 29) { cbo[tid] = bo[tid]; cg[tid] = lng[tid]; cb[tid] = lnb[tid]; }
    for (int i = tid; i < 256 * IND; i += 256) stage[i] = g_data[base + i];
    __syncthreads();

    // LN (own row, stride 29 -> conflict-free)
    float mean = 0.f;
    for (int j = 0; j < IND; j++) mean += stage[tid * IND + j];
    mean *= (1.f / 29.f);
    float var = 0.f;
    for (int j = 0; j < IND; j++) { float d0 = stage[tid * IND + j] - mean; var = fmaf(d0, d0, var); }
    float rstd = rsqrtf(var * (1.f / 29.f) + 1e-5f);

    // q = xn @ Wq, packed pairs along dh
    ull q2[32];
#pragma unroll
    for (int t = 0; t < 32; t++) q2[t] = 0ull;
    for (int j = 0; j < IND; j++) {
        float xn = (stage[tid * IND + j] - mean) * rstd * cg[j] + cb[j];
        ull xj2 = pack2s(xn);
        const ulonglong2* wp = reinterpret_cast<const ulonglong2*>(&Wqs[j * 64]);
#pragma unroll
        for (int t = 0; t < 16; t++) {
            ulonglong2 w = wp[t];
            q2[2 * t]     = fma2(xj2, w.x, q2[2 * t]);
            q2[2 * t + 1] = fma2(xj2, w.y, q2[2 * t + 1]);
        }
    }

    // streaming softmax + AV
    ull out2[32];
#pragma unroll
    for (int t = 0; t < 32; t++) out2[t] = 0ull;
    float ssum = 0.f;
    for (int j = 0; j < NLAT; j++) {
        const ulonglong2* kp = reinterpret_cast<const ulonglong2*>(&Ks[j * 64]);
        ull s2a = 0ull, s2b = 0ull;
#pragma unroll
        for (int t = 0; t < 16; t += 2) {
            ulonglong2 k0 = kp[t], k1 = kp[t + 1];
            s2a = fma2(q2[2 * t + 0], k0.x, s2a);
            s2b = fma2(q2[2 * t + 1], k0.y, s2b);
            s2a = fma2(q2[2 * t + 2], k1.x, s2a);
            s2b = fma2(q2[2 * t + 3], k1.y, s2b);
        }
        float l0, h0, l1, h1;
        unpack2(s2a, l0, h0); unpack2(s2b, l1, h1);
        float p = __expf(((l0 + h0) + (l1 + h1)) * 0.125f);
        ssum += p;
        ull p2 = pack2s(p);
        const ulonglong2* vp = reinterpret_cast<const ulonglong2*>(&Vs[j * 64]);
#pragma unroll
        for (int t = 0; t < 16; t++) {
            ulonglong2 vv = vp[t];
            out2[2 * t]     = fma2(p2, vv.x, out2[2 * t]);
            out2[2 * t + 1] = fma2(p2, vv.y, out2[2 * t + 1]);
        }
    }
    ull inv2 = pack2s(1.f / ssum);
#pragma unroll
    for (int t = 0; t < 32; t++) out2[t] = mul2(out2[t], inv2);

    // out-proj + bias + residual
    for (int c = 0; c < IND; c++) {
        const ulonglong2* wp = reinterpret_cast<const ulonglong2*>(&Wot[c * 64]);
        ull s2a = 0ull, s2b = 0ull;
#pragma unroll
        for (int t = 0; t < 16; t += 2) {
            ulonglong2 w0 = wp[t], w1 = wp[t + 1];
            s2a = fma2(out2[2 * t + 0], w0.x, s2a);
            s2b = fma2(out2[2 * t + 1], w0.y, s2b);
            s2a = fma2(out2[2 * t + 2], w1.x, s2a);
            s2b = fma2(out2[2 * t + 3], w1.y, s2b);
        }
        float l0, h0, l1, h1;
        unpack2(s2a, l0, h0); unpack2(s2b, l1, h1);
        g_data[base + tid * IND + c] = stage[tid * IND + c] + ((l0 + h0) + (l1 + h1)) + cbo[c];
    }
}

// ---------------------------------------------------------------------------
// Fused data GEGLU FF (FFMA2): W1 interleaved (a,g) pairs, W2 padded rows
// ---------------------------------------------------------------------------
__global__ __launch_bounds__(256) void data_ff_k(
    const float* __restrict__ W1, const float* __restrict__ b1,
    const float* __restrict__ W2, const float* __restrict__ b2,
    const float* __restrict__ lng, const float* __restrict__ lnb)
{
    extern __shared__ float sm[];
    float* W1i   = sm;              // 6728 interleaved: [j*232 + 2u+s] = W1[j][s*116+u]
    float* b1i   = W1i + 6728;      // 232 interleaved
    float* W2p   = b1i + 232;       // 116*30 padded
    float* cb2   = W2p + 3480;      // 29
    float* cg    = cb2 + 29;        // 29
    float* cb    = cg + 29;         // 29 (pad 96)
    float* stage = cb2 + 96;        // 7424
    // total = 6728+232+3480+96+7424 = 17960 floats

    const int tid = threadIdx.x;
    const int base = blockIdx.x * 256 * IND;

    for (int i = tid; i < 6728; i += 256) {
        int j = i / 232, r = i - j * 232;
        int u = r >> 1, s = r & 1;
        W1i[i] = W1[j * 232 + s * 116 + u];
    }
    for (int i = tid; i < 116 * 30; i += 256) {
        int u = i / 30, c = i - u * 30;
        W2p[i] = (c < 29) ? W2[u * 29 + c] : 0.f;
    }
    if (tid < 232) { int u = tid >> 1, s = tid & 1; b1i[tid] = b1[s * 116 + u]; }
    if (tid < 29) { cb2[tid] = b2[tid]; cg[tid] = lng[tid]; cb[tid] = lnb[tid]; }
    for (int i = tid; i < 256 * IND; i += 256) stage[i] = g_data[base + i];
    __syncthreads();

    float mean = 0.f;
    for (int j = 0; j < IND; j++) mean += stage[tid * IND + j];
    mean *= (1.f / 29.f);
    float var = 0.f;
    for (int j = 0; j < IND; j++) { float d0 = stage[tid * IND + j] - mean; var = fmaf(d0, d0, var); }
    float rstd = rsqrtf(var * (1.f / 29.f) + 1e-5f);

    ull xp2[29];
#pragma unroll
    for (int j = 0; j < IND; j++) {
        float xn = (stage[tid * IND + j] - mean) * rstd * cg[j] + cb[j];
        xp2[j] = pack2s(xn);
    }

    ull res2[14];
#pragma unroll
    for (int t = 0; t < 14; t++) res2[t] = 0ull;
    float res28 = 0.f;

    for (int u = 0; u < 116; u++) {
        ull agA = *reinterpret_cast<const ull*>(&b1i[2 * u]);
        ull agB = 0ull;
        const float* wrow = &W1i[2 * u];
#pragma unroll
        for (int j = 0; j < 28; j += 2) {
            agA = fma2(xp2[j],     *reinterpret_cast<const ull*>(&wrow[j * 232]),       agA);
            agB = fma2(xp2[j + 1], *reinterpret_cast<const ull*>(&wrow[(j + 1) * 232]), agB);
        }
        agA = fma2(xp2[28], *reinterpret_cast<const ull*>(&wrow[28 * 232]), agA);
        ull ag = add2(agA, agB);
        float a, g; unpack2(ag, a, g);
        float hv = a * 0.5f * g * (1.f + erff(g * 0.70710678118654752f));
        ull hv2 = pack2s(hv);
        const ull* w2r = reinterpret_cast<const ull*>(&W2p[u * 30]);
#pragma unroll
        for (int t = 0; t < 14; t++) res2[t] = fma2(hv2, w2r[t], res2[t]);
        res28 = fmaf(hv, W2p[u * 30 + 28], res28);
    }

    float r[29];
#pragma unroll
    for (int t = 0; t < 14; t++) unpack2(res2[t], r[2 * t], r[2 * t + 1]);
    r[28] = res28;
#pragma unroll
    for (int c = 0; c < IND; c++)
        g_data[base + tid * IND + c] = stage[tid * IND + c] + r[c] + cb2[c];
}

// ---------------------------------------------------------------------------
__global__ void out_kernel(float* __restrict__ out)
{
    int idx = blockIdx.x * blockDim.x + threadIdx.x;
    if (idx >= BB * HW * 3) return;
    int b = idx / (HW * 3);
    int rem = idx - b * HW * 3;
    int p = rem / 3, c = rem - p * 3;
    out[idx] = g_data[(b * HW + p) * IND + c];
}

// ---------------------------------------------------------------------------
extern "C" void kernel_launch(void* const* d_in, const int* in_sizes, int n_in,
                              void* d_out, int out_size)
{
    const float* x         = (const float*)d_in[0];
    const float* latents   = (const float*)d_in[1];
    const float* W_l2l     = (const float*)d_in[2];
    const float* b_l2l     = (const float*)d_in[3];
    const float* ca_ln_q_g = (const float*)d_in[4];
    const float* ca_ln_q_b = (const float*)d_in[5];
    const float* ca_ln_c_g = (const float*)d_in[6];
    const float* ca_ln_c_b = (const float*)d_in[7];
    const float* ca_Wq     = (const float*)d_in[8];
    const float* ca_Wkv    = (const float*)d_in[9];
    const float* ca_Wo     = (const float*)d_in[10];
    const float* ca_bo     = (const float*)d_in[11];
    const float* cf_ln_g   = (const float*)d_in[12];
    const float* cf_ln_b   = (const float*)d_in[13];
    const float* cf_W1     = (const float*)d_in[14];
    const float* cf_b1     = (const float*)d_in[15];
    const float* cf_W2     = (const float*)d_in[16];
    const float* cf_b2     = (const float*)d_in[17];
    const float* la_ln_g   = (const float*)d_in[18];
    const float* la_ln_b   = (const float*)d_in[19];
    const float* la_Wq     = (const float*)d_in[20];
    const float* la_Wkv    = (const float*)d_in[21];
    const float* la_Wo     = (const float*)d_in[22];
    const float* la_bo     = (const float*)d_in[23];
    const float* lf_ln_g   = (const float*)d_in[24];
    const float* lf_ln_b   = (const float*)d_in[25];
    const float* lf_W1     = (const float*)d_in[26];
    const float* lf_b1     = (const float*)d_in[27];
    const float* lf_W2     = (const float*)d_in[28];
    const float* lf_b2     = (const float*)d_in[29];

    float *p_lat, *p_ln, *p_q, *p_kv, *p_ao, *p_ff1, *p_ff2, *p_ckv;
    cudaGetSymbolAddress((void**)&p_lat, g_lat);
    cudaGetSymbolAddress((void**)&p_ln,  g_ln);
    cudaGetSymbolAddress((void**)&p_q,   g_q);
    cudaGetSymbolAddress((void**)&p_kv,  g_kv);
    cudaGetSymbolAddress((void**)&p_ao,  g_ao);
    cudaGetSymbolAddress((void**)&p_ff1, g_ff1);
    cudaGetSymbolAddress((void**)&p_ff2, g_ff2);
    cudaGetSymbolAddress((void**)&p_ckv, g_ckv);

    const int LAT_SMEM   = 2 * NLAT * 64 * 4;                         // 131072 B
    const int CROSS_SMEM = (16384 * 2 + 1856 * 2 + 96 + 7424) * 4;    // 176000 B
    const int FF_SMEM    = (6728 + 232 + 3480 + 96 + 7424) * 4;       // 71840 B
    cudaFuncSetAttribute(lat_attn_k,   cudaFuncAttributeMaxDynamicSharedMemorySize, LAT_SMEM);
    cudaFuncSetAttribute(cross_attn_k, cudaFuncAttributeMaxDynamicSharedMemorySize, CROSS_SMEM);
    cudaFuncSetAttribute(data_ff_k,    cudaFuncAttributeMaxDynamicSharedMemorySize, FF_SMEM);

    l2l_kernel<<<512, 256>>>(x, W_l2l, b_l2l, latents);
    init_data_kernel<<<(HW * IND + 255) / 256, 256>>>();

    for (int i = 0; i < 4; i++) {
        // ---- latent self-attention block ----
        ln512_kernel<<<2048, 128>>>(p_lat, la_ln_g + i * 512, la_ln_b + i * 512, p_ln);
        gemm2_k<64, 128, 8, 4, 8><<<dim3(4, 32), 256>>>(p_ln, la_Wq + (size_t)i * 262144,
                                                        nullptr, nullptr, p_q, 2048, 512, 512);
        gemm2_k<128, 128, 8, 8, 8><<<dim3(8, 16), 256>>>(p_ln, la_Wkv + (size_t)i * 524288,
                                                         nullptr, nullptr, p_kv, 2048, 1024, 512);
        lat_attn_k<<<dim3(8, 8), 256, LAT_SMEM>>>();
        gemm2_k<64, 128, 8, 4, 8><<<dim3(4, 32), 256>>>(p_ao, la_Wo + (size_t)i * 262144,
                                                        la_bo + i * 512, p_lat, p_lat, 2048, 512, 512);
        // ---- latent GEGLU FF ----
        ln512_kernel<<<2048, 128>>>(p_lat, lf_ln_g + i * 512, lf_ln_b + i * 512, p_ln);
        gemm2_k<128, 128, 8, 8, 8><<<dim3(32, 16), 256>>>(p_ln, lf_W1 + (size_t)i * 2097152,
                                                          lf_b1 + i * 4096, nullptr, p_ff1, 2048, 4096, 512);
        geglu_kernel<<<16384, 256>>>();
        gemm2_k<64, 128, 8, 4, 8><<<dim3(4, 32), 256>>>(p_ff2, lf_W2 + (size_t)i * 1048576,
                                                        lf_b2 + i * 512, p_lat, p_lat, 2048, 512, 2048);
        // ---- cross attention (data <- latents) ----
        ln512_kernel<<<2048, 128>>>(p_lat, ca_ln_c_g + i * 512, ca_ln_c_b + i * 512, p_ln);
        gemm2_k<64, 128, 8, 4, 8><<<dim3(1, 32), 256>>>(p_ln, ca_Wkv + (size_t)i * 65536,
                                                        nullptr, nullptr, p_ckv, 2048, 128, 512);
        cross_attn_k<<<dim3(64, 8), 256, CROSS_SMEM>>>(ca_Wq + i * 1856, ca_Wo + i * 1856,
                                                       ca_bo + i * 29, ca_ln_q_g + i * 29, ca_ln_q_b + i * 29);
        // ---- data GEGLU FF ----
        data_ff_k<<<512, 256, FF_SMEM>>>(cf_W1 + i * 6728, cf_b1 + i * 232,
                                         cf_W2 + i * 3364, cf_b2 + i * 29,
                                         cf_ln_g + i * 29, cf_ln_b + i * 29);
    }

    out_kernel<<<(BB * HW * 3 + 255) / 256, 256>>>((float*)d_out);
}

// round 4
// speedup vs baseline: 1.3079x; 1.2032x over previous
#include <cuda_runtime.h>
#include <math.h>

#define BB 8
#define NLAT 256
#define DLAT 512
#define HW 16384
#define IND 29

typedef unsigned long long ull;

// ---------------- f32x2 helpers (FFMA2 path, PTX-only) ----------------------
__device__ __forceinline__ ull pack2(float lo, float hi) {
    ull r; asm("mov.b64 %0, {%1, %2};" : "=l"(r) : "f"(lo), "f"(hi)); return r;
}
__device__ __forceinline__ ull pack2s(float v) { return pack2(v, v); }
__device__ __forceinline__ void unpack2(ull p, float& lo, float& hi) {
    asm("mov.b64 {%0, %1}, %2;" : "=f"(lo), "=f"(hi) : "l"(p));
}
__device__ __forceinline__ ull fma2(ull a, ull b, ull c) {
    ull d; asm("fma.rn.f32x2 %0, %1, %2, %3;" : "=l"(d) : "l"(a), "l"(b), "l"(c)); return d;
}
__device__ __forceinline__ ull add2(ull a, ull b) {
    ull d; asm("add.rn.f32x2 %0, %1, %2;" : "=l"(d) : "l"(a), "l"(b)); return d;
}
__device__ __forceinline__ ull mul2(ull a, ull b) {
    ull d; asm("mul.rn.f32x2 %0, %1, %2;" : "=l"(d) : "l"(a), "l"(b)); return d;
}

// ---------------- scratch (static device globals; no allocation) ------------
__device__ float g_lat [BB * NLAT * DLAT];
__device__ float g_ln  [BB * NLAT * DLAT];
__device__ float g_qkv [BB * NLAT * 1536];
__device__ float g_ao  [BB * NLAT * DLAT];
__device__ float g_ff2 [BB * NLAT * 2048];
__device__ float g_ckv [BB * NLAT * 128];
__device__ float g_data[BB * HW * IND];
__device__ float g_Wqkv[4 * 512 * 1536];

// ---------------------------------------------------------------------------
// pack la_Wq | la_Wkv into one K x 1536 matrix per layer
// ---------------------------------------------------------------------------
__global__ void prep_qkv_w(const float* __restrict__ Wq, const float* __restrict__ Wkv)
{
    int idx = blockIdx.x * 256 + threadIdx.x;      // over 4*512*1536
    if (idx >= 4 * 512 * 1536) return;
    int l = idx / (512 * 1536);
    int r = idx - l * (512 * 1536);
    int k = r / 1536, n = r - k * 1536;
    g_Wqkv[idx] = (n < 512) ? Wq[(size_t)l * 262144 + k * 512 + n]
                            : Wkv[(size_t)l * 524288 + k * 1024 + (n - 512)];
}

// ---------------------------------------------------------------------------
// lat = (x @ W_l2l + b_l2l).reshape(B,N,D) + latents   (HBM-bound)
// ---------------------------------------------------------------------------
__global__ __launch_bounds__(256) void l2l_kernel(
    const float* __restrict__ x, const float* __restrict__ W,
    const float* __restrict__ bias, const float* __restrict__ latents)
{
    __shared__ float xs[4096];
    for (int i = threadIdx.x; i < 4096; i += 256) xs[i] = x[i];
    __syncthreads();
    int j = blockIdx.x * 256 + threadIdx.x;
    float acc[8];
#pragma unroll
    for (int b = 0; b < 8; b++) acc[b] = 0.f;
    const float* wp = W + j;
#pragma unroll 4
    for (int k = 0; k < 512; k++) {
        float w = wp[(size_t)k * 131072];
#pragma unroll
        for (int b = 0; b < 8; b++) acc[b] = fmaf(xs[b * 512 + k], w, acc[b]);
    }
    float add = bias[j] + latents[j];
#pragma unroll
    for (int b = 0; b < 8; b++) g_lat[b * 131072 + j] = acc[b] + add;
}

// ---------------------------------------------------------------------------
// data init
// ---------------------------------------------------------------------------
__global__ void init_data_kernel()
{
    int idx = blockIdx.x * blockDim.x + threadIdx.x;
    if (idx >= HW * IND) return;
    int p = idx / IND, c = idx - p * IND;
    int h = p >> 7, w = p & 127;
    float val = 0.f;
    if (c >= 3) {
        int e = c - 3;
        int axis = e / 13;
        int k = e - axis * 13;
        float coord = -1.f + (2.f / 127.f) * (float)(axis == 0 ? h : w);
        if (k == 12) {
            val = coord;
        } else {
            int band = (k >= 6) ? k - 6 : k;
            float ee = 1.f + (float)band * (1.3219280948873623f / 5.f);
            float sc = exp2f(ee);
            float xp = coord * sc * 3.14159265358979323846f;
            val = (k >= 6) ? cosf(xp) : sinf(xp);
        }
    }
#pragma unroll
    for (int b = 0; b < 8; b++) g_data[b * (HW * IND) + idx] = val;
}

// ---------------------------------------------------------------------------
// LayerNorm over 512
// ---------------------------------------------------------------------------
__global__ __launch_bounds__(128) void ln512_kernel(
    const float* __restrict__ in, const float* __restrict__ gg,
    const float* __restrict__ bbv, float* __restrict__ out)
{
    __shared__ float red[4];
    const int row = blockIdx.x, t = threadIdx.x;
    float4 v = reinterpret_cast<const float4*>(in + row * 512)[t];
    float s = (v.x + v.y) + (v.z + v.w);
#pragma unroll
    for (int o = 16; o; o >>= 1) s += __shfl_xor_sync(0xffffffffu, s, o);
    if ((t & 31) == 0) red[t >> 5] = s;
    __syncthreads();
    float mean = ((red[0] + red[1]) + (red[2] + red[3])) * (1.f / 512.f);
    __syncthreads();
    float dx = v.x - mean, dy = v.y - mean, dz = v.z - mean, dw = v.w - mean;
    float ss = (dx * dx + dy * dy) + (dz * dz + dw * dw);
#pragma unroll
    for (int o = 16; o; o >>= 1) ss += __shfl_xor_sync(0xffffffffu, ss, o);
    if ((t & 31) == 0) red[t >> 5] = ss;
    __syncthreads();
    float var = ((red[0] + red[1]) + (red[2] + red[3])) * (1.f / 512.f);
    float rstd = rsqrtf(var + 1e-5f);
    float4 gv = reinterpret_cast<const float4*>(gg)[t];
    float4 bv = reinterpret_cast<const float4*>(bbv)[t];
    float4 ov;
    ov.x = dx * rstd * gv.x + bv.x;
    ov.y = dy * rstd * gv.y + bv.y;
    ov.z = dz * rstd * gv.z + bv.z;
    ov.w = dw * rstd * gv.w + bv.w;
    reinterpret_cast<float4*>(out + row * 512)[t] = ov;
}

// ---------------------------------------------------------------------------
// Double-buffered FFMA2 GEMM: C = A @ B [+bias(N)] [+res]
// One __syncthreads per BK=16 k-steps; gmem loads staged 2 tiles ahead.
// ---------------------------------------------------------------------------
template <int BM, int BN, int BK, int TM, int TN, int NT>
__global__ __launch_bounds__(NT) void gemm_db_k(
    const float* __restrict__ A, const float* __restrict__ Bm,
    const float* __restrict__ bias, const float* __restrict__ res,
    float* __restrict__ C, int M, int N, int K)
{
    constexpr int LDA = BM + 4;
    constexpr int NTX = BN / TN;
    constexpr int AF4 = BM * BK / (4 * NT);
    constexpr int BF4 = BK * BN / (4 * NT);
    constexpr int KQ  = BK / 4;
    __shared__ float As[2][BK][LDA];
    __shared__ float Bs[2][BK][BN];
    const int bm = blockIdx.y * BM, bn = blockIdx.x * BN;
    const int tid = threadIdx.x;
    const int tx = tid % NTX, ty = tid / NTX;

    ull acc[TM][TN / 2];
#pragma unroll
    for (int i = 0; i < TM; i++)
#pragma unroll
        for (int j = 0; j < TN / 2; j++) acc[i][j] = 0ull;

    float4 ra[AF4], rb[BF4];

    auto loadT = [&](int k0) {
#pragma unroll
        for (int i = 0; i < AF4; i++) {
            int idx = i * NT + tid;
            int r = idx / KQ, q = idx - r * KQ;
            ra[i] = *reinterpret_cast<const float4*>(&A[(size_t)(bm + r) * K + k0 + q * 4]);
        }
#pragma unroll
        for (int i = 0; i < BF4; i++) {
            int idx = i * NT + tid;
            int r = idx / (BN / 4), c = idx - r * (BN / 4);
            rb[i] = *reinterpret_cast<const float4*>(&Bm[(size_t)(k0 + r) * N + bn + c * 4]);
        }
    };
    auto storeT = [&](int buf) {
#pragma unroll
        for (int i = 0; i < AF4; i++) {
            int idx = i * NT + tid;
            int r = idx / KQ, q = idx - r * KQ;
            As[buf][q * 4 + 0][r] = ra[i].x;
            As[buf][q * 4 + 1][r] = ra[i].y;
            As[buf][q * 4 + 2][r] = ra[i].z;
            As[buf][q * 4 + 3][r] = ra[i].w;
        }
#pragma unroll
        for (int i = 0; i < BF4; i++) {
            int idx = i * NT + tid;
            int r = idx / (BN / 4), c = idx - r * (BN / 4);
            *reinterpret_cast<float4*>(&Bs[buf][r][c * 4]) = rb[i];
        }
    };

    const int T = K / BK;
    loadT(0);
    storeT(0);
    if (T > 1) loadT(BK);
    for (int t = 0; t < T; t++) {
        __syncthreads();
        if (t + 1 < T) storeT((t + 1) & 1);
        if (t + 2 < T) loadT((t + 2) * BK);
        const int buf = t & 1;
#pragma unroll
        for (int k = 0; k < BK; k++) {
            ull b2[TN / 2];
            const ulonglong2* bp = reinterpret_cast<const ulonglong2*>(&Bs[buf][k][tx * TN]);
#pragma unroll
            for (int j = 0; j < TN / 4; j++) {
                ulonglong2 t2 = bp[j];
                b2[2 * j] = t2.x; b2[2 * j + 1] = t2.y;
            }
            ull ap[TM];
#pragma unroll
            for (int i = 0; i < TM; i += 4) {
                float4 av = *reinterpret_cast<const float4*>(&As[buf][k][ty * TM + i]);
                ap[i + 0] = pack2s(av.x); ap[i + 1] = pack2s(av.y);
                ap[i + 2] = pack2s(av.z); ap[i + 3] = pack2s(av.w);
            }
#pragma unroll
            for (int i = 0; i < TM; i++)
#pragma unroll
                for (int j = 0; j < TN / 2; j++)
                    acc[i][j] = fma2(ap[i], b2[j], acc[i][j]);
        }
    }

    float bv[TN];
#pragma unroll
    for (int j = 0; j < TN; j++) bv[j] = 0.f;
    if (bias) {
#pragma unroll
        for (int j = 0; j < TN; j += 4) {
            float4 t = *reinterpret_cast<const float4*>(&bias[bn + tx * TN + j]);
            bv[j] = t.x; bv[j + 1] = t.y; bv[j + 2] = t.z; bv[j + 3] = t.w;
        }
    }
#pragma unroll
    for (int i = 0; i < TM; i++) {
        size_t row = (size_t)(bm + ty * TM + i);
        float o[TN];
#pragma unroll
        for (int j = 0; j < TN / 2; j++) unpack2(acc[i][j], o[2 * j], o[2 * j + 1]);
#pragma unroll
        for (int j = 0; j < TN; j++) o[j] += bv[j];
        if (res) {
#pragma unroll
            for (int j = 0; j < TN; j += 4) {
                float4 t = *reinterpret_cast<const float4*>(&res[row * N + bn + tx * TN + j]);
                o[j] += t.x; o[j + 1] += t.y; o[j + 2] += t.z; o[j + 3] += t.w;
            }
        }
#pragma unroll
        for (int j = 0; j < TN; j += 4) {
            float4 t; t.x = o[j]; t.y = o[j + 1]; t.z = o[j + 2]; t.w = o[j + 3];
            *reinterpret_cast<float4*>(&C[row * N + bn + tx * TN + j]) = t;
        }
    }
}

// ---------------------------------------------------------------------------
// FF1 GEMM with fused GEGLU epilogue. A: 2048xK, W1: Kx4096 ([a|g] halves).
// CTA bx owns a-cols [bx*64,+64) paired with g-cols [2048+bx*64,+64).
// Writes C (2048 x 2048) = (a+ba) * gelu(g+bg). grid (32, 16), 256 thr.
// ---------------------------------------------------------------------------
__global__ __launch_bounds__(256) void gemm_geglu_k(
    const float* __restrict__ A, const float* __restrict__ W1,
    const float* __restrict__ b1, float* __restrict__ C, int K)
{
    constexpr int BM = 128, BK = 16, NT = 256, LDA = BM + 4;
    __shared__ float As[2][BK][LDA];
    __shared__ float Bs[2][BK][128];
    const int bm = blockIdx.y * BM;
    const int bnA = blockIdx.x * 64;
    const int tid = threadIdx.x;
    const int tx = tid % 16, ty = tid / 16;

    ull acc[8][4];
#pragma unroll
    for (int i = 0; i < 8; i++)
#pragma unroll
        for (int j = 0; j < 4; j++) acc[i][j] = 0ull;

    float4 ra[2], rb[2];
    auto loadT = [&](int k0) {
#pragma unroll
        for (int i = 0; i < 2; i++) {
            int idx = i * NT + tid;
            int r = idx / 4, q = idx & 3;
            ra[i] = *reinterpret_cast<const float4*>(&A[(size_t)(bm + r) * K + k0 + q * 4]);
        }
#pragma unroll
        for (int i = 0; i < 2; i++) {
            int idx = i * NT + tid;
            int r = idx / 32, c = (idx & 31) * 4;
            int gc = (c < 64) ? (bnA + c) : (2048 + bnA + (c - 64));
            rb[i] = *reinterpret_cast<const float4*>(&W1[(size_t)(k0 + r) * 4096 + gc]);
        }
    };
    auto storeT = [&](int buf) {
#pragma unroll
        for (int i = 0; i < 2; i++) {
            int idx = i * NT + tid;
            int r = idx / 4, q = idx & 3;
            As[buf][q * 4 + 0][r] = ra[i].x;
            As[buf][q * 4 + 1][r] = ra[i].y;
            As[buf][q * 4 + 2][r] = ra[i].z;
            As[buf][q * 4 + 3][r] = ra[i].w;
        }
#pragma unroll
        for (int i = 0; i < 2; i++) {
            int idx = i * NT + tid;
            int r = idx / 32, c = (idx & 31) * 4;
            *reinterpret_cast<float4*>(&Bs[buf][r][c]) = rb[i];
        }
    };

    const int T = K / BK;
    loadT(0);
    storeT(0);
    if (T > 1) loadT(BK);
    for (int t = 0; t < T; t++) {
        __syncthreads();
        if (t + 1 < T) storeT((t + 1) & 1);
        if (t + 2 < T) loadT((t + 2) * BK);
        const int buf = t & 1;
#pragma unroll
        for (int k = 0; k < BK; k++) {
            ulonglong2 ba2 = *reinterpret_cast<const ulonglong2*>(&Bs[buf][k][tx * 4]);
            ulonglong2 bg2 = *reinterpret_cast<const ulonglong2*>(&Bs[buf][k][64 + tx * 4]);
            ull b2[4] = { ba2.x, ba2.y, bg2.x, bg2.y };
            ull ap[8];
#pragma unroll
            for (int i = 0; i < 8; i += 4) {
                float4 av = *reinterpret_cast<const float4*>(&As[buf][k][ty * 8 + i]);
                ap[i + 0] = pack2s(av.x); ap[i + 1] = pack2s(av.y);
                ap[i + 2] = pack2s(av.z); ap[i + 3] = pack2s(av.w);
            }
#pragma unroll
            for (int i = 0; i < 8; i++)
#pragma unroll
                for (int j = 0; j < 4; j++)
                    acc[i][j] = fma2(ap[i], b2[j], acc[i][j]);
        }
    }

    float4 bat = *reinterpret_cast<const float4*>(&b1[bnA + tx * 4]);
    float4 bgt = *reinterpret_cast<const float4*>(&b1[2048 + bnA + tx * 4]);
    float ba[4] = { bat.x, bat.y, bat.z, bat.w };
    float bg[4] = { bgt.x, bgt.y, bgt.z, bgt.w };
#pragma unroll
    for (int i = 0; i < 8; i++) {
        size_t row = (size_t)(bm + ty * 8 + i);
        float a[4], g[4];
        unpack2(acc[i][0], a[0], a[1]); unpack2(acc[i][1], a[2], a[3]);
        unpack2(acc[i][2], g[0], g[1]); unpack2(acc[i][3], g[2], g[3]);
        float4 o;
        float* op = &o.x;
#pragma unroll
        for (int e = 0; e < 4; e++) {
            float av = a[e] + ba[e];
            float gv = g[e] + bg[e];
            op[e] = av * 0.5f * gv * (1.f + erff(gv * 0.70710678118654752f));
        }
        *reinterpret_cast<float4*>(&C[row * 2048 + bnA + tx * 4]) = o;
    }
}

// ---------------------------------------------------------------------------
// Latent self-attn (8 heads, dh=64): reads fused qkv (row stride 1536)
// ---------------------------------------------------------------------------
__global__ __launch_bounds__(256) void lat_attn_k()
{
    extern __shared__ float sm[];
    float* Ks = sm;
    float* Vs = sm + NLAT * 64;
    const int h = blockIdx.x, b = blockIdx.y;
    const int tid = threadIdx.x;

    for (int i = tid; i < NLAT * 64; i += 256) {
        int j = i >> 6, d = i & 63;
        Ks[i] = g_qkv[(size_t)(b * NLAT + j) * 1536 + 512 + h * 64 + d];
        Vs[i] = g_qkv[(size_t)(b * NLAT + j) * 1536 + 1024 + h * 64 + d];
    }
    __syncthreads();

    ull q2[32];
    {
        const ulonglong2* qg = reinterpret_cast<const ulonglong2*>(
            &g_qkv[(size_t)(b * NLAT + tid) * 1536 + h * 64]);
#pragma unroll
        for (int t = 0; t < 16; t++) { ulonglong2 v = qg[t]; q2[2 * t] = v.x; q2[2 * t + 1] = v.y; }
    }
    ull out2[32];
#pragma unroll
    for (int t = 0; t < 32; t++) out2[t] = 0ull;
    float ssum = 0.f;

    for (int j = 0; j < NLAT; j++) {
        const ulonglong2* kp = reinterpret_cast<const ulonglong2*>(&Ks[j * 64]);
        ull s2a = 0ull, s2b = 0ull;
#pragma unroll
        for (int t = 0; t < 16; t += 2) {
            ulonglong2 k0 = kp[t], k1 = kp[t + 1];
            s2a = fma2(q2[2 * t + 0], k0.x, s2a);
            s2b = fma2(q2[2 * t + 1], k0.y, s2b);
            s2a = fma2(q2[2 * t + 2], k1.x, s2a);
            s2b = fma2(q2[2 * t + 3], k1.y, s2b);
        }
        float l0, h0, l1, h1;
        unpack2(s2a, l0, h0); unpack2(s2b, l1, h1);
        float p = __expf(((l0 + h0) + (l1 + h1)) * 0.125f);
        ssum += p;
        ull p2 = pack2s(p);
        const ulonglong2* vp = reinterpret_cast<const ulonglong2*>(&Vs[j * 64]);
#pragma unroll
        for (int t = 0; t < 16; t++) {
            ulonglong2 vv = vp[t];
            out2[2 * t]     = fma2(p2, vv.x, out2[2 * t]);
            out2[2 * t + 1] = fma2(p2, vv.y, out2[2 * t + 1]);
        }
    }
    ull inv2 = pack2s(1.f / ssum);
    float* og = &g_ao[(size_t)(b * NLAT + tid) * 512 + h * 64];
#pragma unroll
    for (int t = 0; t < 16; t++) {
        ull r0 = mul2(out2[2 * t], inv2), r1 = mul2(out2[2 * t + 1], inv2);
        float4 w;
        unpack2(r0, w.x, w.y); unpack2(r1, w.z, w.w);
        reinterpret_cast<float4*>(og)[t] = w;
    }
}

// ---------------------------------------------------------------------------
// Fused cross-attention (FFMA2)
// ---------------------------------------------------------------------------
__global__ __launch_bounds__(256) void cross_attn_k(
    const float* __restrict__ Wq, const float* __restrict__ Wo,
    const float* __restrict__ bo, const float* __restrict__ lng,
    const float* __restrict__ lnb)
{
    extern __shared__ float sm[];
    float* Ks    = sm;
    float* Vs    = Ks + 16384;
    float* Wqs   = Vs + 16384;
    float* Wot   = Wqs + 1856;
    float* cbo   = Wot + 1856;
    float* cg    = cbo + 29;
    float* cb    = cg + 29;
    float* stage = cbo + 96;

    const int b = blockIdx.y;
    const int tid = threadIdx.x;
    const int base = (b * HW + blockIdx.x * 256) * IND;

    for (int i = tid; i < 16384; i += 256) {
        int j = i >> 6, d = i & 63;
        Ks[i] = g_ckv[(b * NLAT + j) * 128 + d];
        Vs[i] = g_ckv[(b * NLAT + j) * 128 + 64 + d];
    }
    for (int i = tid; i < 1856; i += 256) {
        Wqs[i] = Wq[i];
        Wot[i] = Wo[(i & 63) * IND + (i >> 6)];
    }
    if (tid < 29) { cbo[tid] = bo[tid]; cg[tid] = lng[tid]; cb[tid] = lnb[tid]; }
    for (int i = tid; i < 256 * IND; i += 256) stage[i] = g_data[base + i];
    __syncthreads();

    float mean = 0.f;
    for (int j = 0; j < IND; j++) mean += stage[tid * IND + j];
    mean *= (1.f / 29.f);
    float var = 0.f;
    for (int j = 0; j < IND; j++) { float d0 = stage[tid * IND + j] - mean; var = fmaf(d0, d0, var); }
    float rstd = rsqrtf(var * (1.f / 29.f) + 1e-5f);

    ull q2[32];
#pragma unroll
    for (int t = 0; t < 32; t++) q2[t] = 0ull;
    for (int j = 0; j < IND; j++) {
        float xn = (stage[tid * IND + j] - mean) * rstd * cg[j] + cb[j];
        ull xj2 = pack2s(xn);
        const ulonglong2* wp = reinterpret_cast<const ulonglong2*>(&Wqs[j * 64]);
#pragma unroll
        for (int t = 0; t < 16; t++) {
            ulonglong2 w = wp[t];
            q2[2 * t]     = fma2(xj2, w.x, q2[2 * t]);
            q2[2 * t + 1] = fma2(xj2, w.y, q2[2 * t + 1]);
        }
    }

    ull out2[32];
#pragma unroll
    for (int t = 0; t < 32; t++) out2[t] = 0ull;
    float ssum = 0.f;
    for (int j = 0; j < NLAT; j++) {
        const ulonglong2* kp = reinterpret_cast<const ulonglong2*>(&Ks[j * 64]);
        ull s2a = 0ull, s2b = 0ull;
#pragma unroll
        for (int t = 0; t < 16; t += 2) {
            ulonglong2 k0 = kp[t], k1 = kp[t + 1];
            s2a = fma2(q2[2 * t + 0], k0.x, s2a);
            s2b = fma2(q2[2 * t + 1], k0.y, s2b);
            s2a = fma2(q2[2 * t + 2], k1.x, s2a);
            s2b = fma2(q2[2 * t + 3], k1.y, s2b);
        }
        float l0, h0, l1, h1;
        unpack2(s2a, l0, h0); unpack2(s2b, l1, h1);
        float p = __expf(((l0 + h0) + (l1 + h1)) * 0.125f);
        ssum += p;
        ull p2 = pack2s(p);
        const ulonglong2* vp = reinterpret_cast<const ulonglong2*>(&Vs[j * 64]);
#pragma unroll
        for (int t = 0; t < 16; t++) {
            ulonglong2 vv = vp[t];
            out2[2 * t]     = fma2(p2, vv.x, out2[2 * t]);
            out2[2 * t + 1] = fma2(p2, vv.y, out2[2 * t + 1]);
        }
    }
    ull inv2 = pack2s(1.f / ssum);
#pragma unroll
    for (int t = 0; t < 32; t++) out2[t] = mul2(out2[t], inv2);

    for (int c = 0; c < IND; c++) {
        const ulonglong2* wp = reinterpret_cast<const ulonglong2*>(&Wot[c * 64]);
        ull s2a = 0ull, s2b = 0ull;
#pragma unroll
        for (int t = 0; t < 16; t += 2) {
            ulonglong2 w0 = wp[t], w1 = wp[t + 1];
            s2a = fma2(out2[2 * t + 0], w0.x, s2a);
            s2b = fma2(out2[2 * t + 1], w0.y, s2b);
            s2a = fma2(out2[2 * t + 2], w1.x, s2a);
            s2b = fma2(out2[2 * t + 3], w1.y, s2b);
        }
        float l0, h0, l1, h1;
        unpack2(s2a, l0, h0); unpack2(s2b, l1, h1);
        g_data[base + tid * IND + c] = stage[tid * IND + c] + ((l0 + h0) + (l1 + h1)) + cbo[c];
    }
}

// ---------------------------------------------------------------------------
// Fused data GEGLU FF (FFMA2)
// ---------------------------------------------------------------------------
__global__ __launch_bounds__(256) void data_ff_k(
    const float* __restrict__ W1, const float* __restrict__ b1,
    const float* __restrict__ W2, const float* __restrict__ b2,
    const float* __restrict__ lng, const float* __restrict__ lnb)
{
    extern __shared__ float sm[];
    float* W1i   = sm;
    float* b1i   = W1i + 6728;
    float* W2p   = b1i + 232;
    float* cb2   = W2p + 3480;
    float* cg    = cb2 + 29;
    float* cb    = cg + 29;
    float* stage = cb2 + 96;

    const int tid = threadIdx.x;
    const int base = blockIdx.x * 256 * IND;

    for (int i = tid; i < 6728; i += 256) {
        int j = i / 232, r = i - j * 232;
        int u = r >> 1, s = r & 1;
        W1i[i] = W1[j * 232 + s * 116 + u];
    }
    for (int i = tid; i < 116 * 30; i += 256) {
        int u = i / 30, c = i - u * 30;
        W2p[i] = (c < 29) ? W2[u * 29 + c] : 0.f;
    }
    if (tid < 232) { int u = tid >> 1, s = tid & 1; b1i[tid] = b1[s * 116 + u]; }
    if (tid < 29) { cb2[tid] = b2[tid]; cg[tid] = lng[tid]; cb[tid] = lnb[tid]; }
    for (int i = tid; i < 256 * IND; i += 256) stage[i] = g_data[base + i];
    __syncthreads();

    float mean = 0.f;
    for (int j = 0; j < IND; j++) mean += stage[tid * IND + j];
    mean *= (1.f / 29.f);
    float var = 0.f;
    for (int j = 0; j < IND; j++) { float d0 = stage[tid * IND + j] - mean; var = fmaf(d0, d0, var); }
    float rstd = rsqrtf(var * (1.f / 29.f) + 1e-5f);

    ull xp2[29];
#pragma unroll
    for (int j = 0; j < IND; j++) {
        float xn = (stage[tid * IND + j] - mean) * rstd * cg[j] + cb[j];
        xp2[j] = pack2s(xn);
    }

    ull res2[14];
#pragma unroll
    for (int t = 0; t < 14; t++) res2[t] = 0ull;
    float res28 = 0.f;

    for (int u = 0; u < 116; u++) {
        ull agA = *reinterpret_cast<const ull*>(&b1i[2 * u]);
        ull agB = 0ull;
        const float* wrow = &W1i[2 * u];
#pragma unroll
        for (int j = 0; j < 28; j += 2) {
            agA = fma2(xp2[j],     *reinterpret_cast<const ull*>(&wrow[j * 232]),       agA);
            agB = fma2(xp2[j + 1], *reinterpret_cast<const ull*>(&wrow[(j + 1) * 232]), agB);
        }
        agA = fma2(xp2[28], *reinterpret_cast<const ull*>(&wrow[28 * 232]), agA);
        ull ag = add2(agA, agB);
        float a, g; unpack2(ag, a, g);
        float hv = a * 0.5f * g * (1.f + erff(g * 0.70710678118654752f));
        ull hv2 = pack2s(hv);
        const ull* w2r = reinterpret_cast<const ull*>(&W2p[u * 30]);
#pragma unroll
        for (int t = 0; t < 14; t++) res2[t] = fma2(hv2, w2r[t], res2[t]);
        res28 = fmaf(hv, W2p[u * 30 + 28], res28);
    }

    float r[29];
#pragma unroll
    for (int t = 0; t < 14; t++) unpack2(res2[t], r[2 * t], r[2 * t + 1]);
    r[28] = res28;
#pragma unroll
    for (int c = 0; c < IND; c++)
        g_data[base + tid * IND + c] = stage[tid * IND + c] + r[c] + cb2[c];
}

// ---------------------------------------------------------------------------
__global__ void out_kernel(float* __restrict__ out)
{
    int idx = blockIdx.x * blockDim.x + threadIdx.x;
    if (idx >= BB * HW * 3) return;
    int b = idx / (HW * 3);
    int rem = idx - b * HW * 3;
    int p = rem / 3, c = rem - p * 3;
    out[idx] = g_data[(b * HW + p) * IND + c];
}

// ---------------------------------------------------------------------------
extern "C" void kernel_launch(void* const* d_in, const int* in_sizes, int n_in,
                              void* d_out, int out_size)
{
    const float* x         = (const float*)d_in[0];
    const float* latents   = (const float*)d_in[1];
    const float* W_l2l     = (const float*)d_in[2];
    const float* b_l2l     = (const float*)d_in[3];
    const float* ca_ln_q_g = (const float*)d_in[4];
    const float* ca_ln_q_b = (const float*)d_in[5];
    const float* ca_ln_c_g = (const float*)d_in[6];
    const float* ca_ln_c_b = (const float*)d_in[7];
    const float* ca_Wq     = (const float*)d_in[8];
    const float* ca_Wkv    = (const float*)d_in[9];
    const float* ca_Wo     = (const float*)d_in[10];
    const float* ca_bo     = (const float*)d_in[11];
    const float* cf_ln_g   = (const float*)d_in[12];
    const float* cf_ln_b   = (const float*)d_in[13];
    const float* cf_W1     = (const float*)d_in[14];
    const float* cf_b1     = (const float*)d_in[15];
    const float* cf_W2     = (const float*)d_in[16];
    const float* cf_b2     = (const float*)d_in[17];
    const float* la_ln_g   = (const float*)d_in[18];
    const float* la_ln_b   = (const float*)d_in[19];
    const float* la_Wq     = (const float*)d_in[20];
    const float* la_Wkv    = (const float*)d_in[21];
    const float* la_Wo     = (const float*)d_in[22];
    const float* la_bo     = (const float*)d_in[23];
    const float* lf_ln_g   = (const float*)d_in[24];
    const float* lf_ln_b   = (const float*)d_in[25];
    const float* lf_W1     = (const float*)d_in[26];
    const float* lf_b1     = (const float*)d_in[27];
    const float* lf_W2     = (const float*)d_in[28];
    const float* lf_b2     = (const float*)d_in[29];

    float *p_lat, *p_ln, *p_qkv, *p_ao, *p_ff2, *p_ckv, *p_wqkv;
    cudaGetSymbolAddress((void**)&p_lat,  g_lat);
    cudaGetSymbolAddress((void**)&p_ln,   g_ln);
    cudaGetSymbolAddress((void**)&p_qkv,  g_qkv);
    cudaGetSymbolAddress((void**)&p_ao,   g_ao);
    cudaGetSymbolAddress((void**)&p_ff2,  g_ff2);
    cudaGetSymbolAddress((void**)&p_ckv,  g_ckv);
    cudaGetSymbolAddress((void**)&p_wqkv, g_Wqkv);

    const int LAT_SMEM   = 2 * NLAT * 64 * 4;
    const int CROSS_SMEM = (16384 * 2 + 1856 * 2 + 96 + 7424) * 4;
    const int FF_SMEM    = (6728 + 232 + 3480 + 96 + 7424) * 4;
    cudaFuncSetAttribute(lat_attn_k,   cudaFuncAttributeMaxDynamicSharedMemorySize, LAT_SMEM);
    cudaFuncSetAttribute(cross_attn_k, cudaFuncAttributeMaxDynamicSharedMemorySize, CROSS_SMEM);
    cudaFuncSetAttribute(data_ff_k,    cudaFuncAttributeMaxDynamicSharedMemorySize, FF_SMEM);

    prep_qkv_w<<<(4 * 512 * 1536 + 255) / 256, 256>>>(la_Wq, la_Wkv);
    l2l_kernel<<<512, 256>>>(x, W_l2l, b_l2l, latents);
    init_data_kernel<<<(HW * IND + 255) / 256, 256>>>();

    for (int i = 0; i < 4; i++) {
        // ---- latent self-attention block ----
        ln512_kernel<<<2048, 128>>>(p_lat, la_ln_g + i * 512, la_ln_b + i * 512, p_ln);
        gemm_db_k<128, 128, 16, 8, 8, 256><<<dim3(12, 16), 256>>>(
            p_ln, p_wqkv + (size_t)i * 786432, nullptr, nullptr, p_qkv, 2048, 1536, 512);
        lat_attn_k<<<dim3(8, 8), 256, LAT_SMEM>>>();
        gemm_db_k<64, 64, 16, 4, 8, 128><<<dim3(8, 32), 128>>>(
            p_ao, la_Wo + (size_t)i * 262144, la_bo + i * 512, p_lat, p_lat, 2048, 512, 512);
        // ---- latent GEGLU FF ----
        ln512_kernel<<<2048, 128>>>(p_lat, lf_ln_g + i * 512, lf_ln_b + i * 512, p_ln);
        gemm_geglu_k<<<dim3(32, 16), 256>>>(p_ln, lf_W1 + (size_t)i * 2097152,
                                            lf_b1 + i * 4096, p_ff2, 512);
        gemm_db_k<64, 64, 16, 4, 8, 128><<<dim3(8, 32), 128>>>(
            p_ff2, lf_W2 + (size_t)i * 1048576, lf_b2 + i * 512, p_lat, p_lat, 2048, 512, 2048);
        // ---- cross attention (data <- latents) ----
        ln512_kernel<<<2048, 128>>>(p_lat, ca_ln_c_g + i * 512, ca_ln_c_b + i * 512, p_ln);
        gemm_db_k<64, 64, 16, 4, 8, 128><<<dim3(2, 32), 128>>>(
            p_ln, ca_Wkv + (size_t)i * 65536, nullptr, nullptr, p_ckv, 2048, 128, 512);
        cross_attn_k<<<dim3(64, 8), 256, CROSS_SMEM>>>(ca_Wq + i * 1856, ca_Wo + i * 1856,
                                                       ca_bo + i * 29, ca_ln_q_g + i * 29, ca_ln_q_b + i * 29);
        // ---- data GEGLU FF ----
        data_ff_k<<<512, 256, FF_SMEM>>>(cf_W1 + i * 6728, cf_b1 + i * 232,
                                         cf_W2 + i * 3364, cf_b2 + i * 29,
                                         cf_ln_g + i * 29, cf_ln_b + i * 29);
    }

    out_kernel<<<(BB * HW * 3 + 255) / 256, 256>>>((float*)d_out);
}